// round 3
// baseline (speedup 1.0000x reference)
#include <cuda_runtime.h>

#define DIM 4096
#define THREADS 256   // one row per CTA, 8 warps, 16 regs/thread

// Layout A (exchange 1): e + 4*(e>>4) + 16*(e>>8)  -> 5376 floats
// Layout B (exchange 2): e + 16*(e>>8)             -> 4352 floats
#define SMEM_WORDS 5376

__device__ __forceinline__ void bfly(float& a, float& b) {
    float s = a + b;
    float d = a - b;
    a = s; b = d;
}

__global__ __launch_bounds__(THREADS, 8)
void fwht4096_hiocc_kernel(const float* __restrict__ x, float* __restrict__ out) {
    __shared__ float s[SMEM_WORDS];  // 21504 B

    const int row = blockIdx.x;
    const int t = threadIdx.x;

    const float4* __restrict__ xin =
        reinterpret_cast<const float4*>(x + (size_t)row * DIM);
    float* __restrict__ orow = out + (size_t)row * DIM;

    // ================= Phase 1: e = k + 16*t  (reg bits = e-bits 0..3) ======
    float v[16];
#pragma unroll
    for (int q = 0; q < 4; q++) {
        float4 f = __ldcs(xin + 4 * t + q);   // streaming load, coalesced
        v[4 * q + 0] = f.x;
        v[4 * q + 1] = f.y;
        v[4 * q + 2] = f.z;
        v[4 * q + 3] = f.w;
    }

#pragma unroll
    for (int h = 1; h <= 8; h <<= 1) {
#pragma unroll
        for (int k = 0; k < 16; k++)
            if (!(k & h)) bfly(v[k], v[k ^ h]);
    }

    // store layout A: addr = k + 20*t + 16*(t>>4)  (float4, conflict-free)
    {
        const int baseA = 20 * t + 16 * (t >> 4);
#pragma unroll
        for (int q = 0; q < 4; q++) {
            *reinterpret_cast<float4*>(&s[baseA + 4 * q]) =
                make_float4(v[4 * q + 0], v[4 * q + 1], v[4 * q + 2], v[4 * q + 3]);
        }
    }
    __syncthreads();

    // ================= Phase 2: e = (t&15) + 16*j + 256*(t>>4) =============
    // reg bits j = e-bits 4..7
    float u[16];
    {
        const int klo2 = t & 15;
        const int m = t >> 4;
        const int base2 = klo2 + 336 * m;  // layout A: klo2 + 20j + 336m
#pragma unroll
        for (int j = 0; j < 16; j++) u[j] = s[base2 + 20 * j];
    }

#pragma unroll
    for (int h = 1; h <= 8; h <<= 1) {
#pragma unroll
        for (int j = 0; j < 16; j++)
            if (!(j & h)) bfly(u[j], u[j ^ h]);
    }

    // barrier before switching the buffer to layout B (addresses alias A)
    __syncthreads();

    // store layout B: addr = klo2 + 16*j + 272*m  (conflict-free: 272%32==16)
    {
        const int klo2 = t & 15;
        const int m = t >> 4;
        const int baseB = klo2 + 272 * m;
#pragma unroll
        for (int j = 0; j < 16; j++) s[baseB + 16 * j] = u[j];
    }
    __syncthreads();

    // ================= Phase 3: e = t + 256*k  (reg bits = e-bits 8..11) ===
    float w[16];
#pragma unroll
    for (int k = 0; k < 16; k++) w[k] = s[t + 272 * k];  // bank = lane, perfect

#pragma unroll
    for (int h = 1; h <= 8; h <<= 1) {
#pragma unroll
        for (int k = 0; k < 16; k++)
            if (!(k & h)) bfly(w[k], w[k ^ h]);
    }

    // scalar but fully coalesced streaming stores (32 contiguous floats/warp)
#pragma unroll
    for (int k = 0; k < 16; k++)
        __stcs(orow + t + 256 * k, w[k]);
}

extern "C" void kernel_launch(void* const* d_in, const int* in_sizes, int n_in,
                              void* d_out, int out_size) {
    // x is the input whose element count equals out_size (N_TOKENS*DIM);
    // H is implicit in the transform and never read.
    const float* x = (const float*)d_in[0];
    for (int i = 0; i < n_in; i++) {
        if (in_sizes[i] == out_size) { x = (const float*)d_in[i]; break; }
    }
    float* out = (float*)d_out;
    const int n_rows = out_size / DIM;  // 8192
    fwht4096_hiocc_kernel<<<n_rows, THREADS>>>(x, out);
}